// round 3
// baseline (speedup 1.0000x reference)
#include <cuda_runtime.h>
#include <math.h>
#include <stdint.h>

// ---------------------------------------------------------------------------
// Problem constants
// ---------------------------------------------------------------------------
#define BATCH   65536
#define DIN     118
#define NS      128          // ODE state dim (118 + 10 aug)
#define NH      256          // hidden dim
#define NOUTC   10           // output dim
#define NEL     (BATCH*NS)   // 8388608 state elements
#define ROWS_PB 64           // batch rows per block in fused MLP
#define NBLK    (BATCH/ROWS_PB)   // 1024 blocks
#define MAXIT   64           // attempt budget (dopri5 attempts incl. rejects)
#define RTOLv   1e-3f
#define ATOLv   1e-3f
#define LDA     68           // smem K-major row stride (64 rows + 4 pad)

#define SMEM_FLOATS (128*LDA + 256*LDA + 256*LDA + 128*64)
#define SMEM_BYTES  (SMEM_FLOATS*4)

// ---------------------------------------------------------------------------
// Device global scratch (static __device__ arrays: no runtime allocation)
// ---------------------------------------------------------------------------
__device__ float g_ybuf[2][NEL];   // double-buffered state y
__device__ float g_k[7][NEL];      // RK stages; slots {0,6} swap as k1/k7 (FSAL)

struct Ctrl {
    double sum0, sum1, sum2, errsum;
    float  t, dt, dt_last, last_t, h0, d1;
    int    done, cur, k0slot;
};
__device__ Ctrl g_ctrl;

// ---------------------------------------------------------------------------
// Dopri5 tableau (exactly as jax.experimental.ode, double -> float)
// ---------------------------------------------------------------------------
__constant__ float c_beta[6][6] = {
    {(float)(1.0/5.0), 0.f, 0.f, 0.f, 0.f, 0.f},
    {(float)(3.0/40.0), (float)(9.0/40.0), 0.f, 0.f, 0.f, 0.f},
    {(float)(44.0/45.0), (float)(-56.0/15.0), (float)(32.0/9.0), 0.f, 0.f, 0.f},
    {(float)(19372.0/6561.0), (float)(-25360.0/2187.0), (float)(64448.0/6561.0),
     (float)(-212.0/729.0), 0.f, 0.f},
    {(float)(9017.0/3168.0), (float)(-355.0/33.0), (float)(46732.0/5247.0),
     (float)(49.0/176.0), (float)(-5103.0/18656.0), 0.f},
    {(float)(35.0/384.0), 0.f, (float)(500.0/1113.0), (float)(125.0/192.0),
     (float)(-2187.0/6784.0), (float)(11.0/84.0)}
};
__constant__ float c_errv[7] = {
    (float)(35.0/384.0 - 1951.0/21600.0), 0.f,
    (float)(500.0/1113.0 - 22642.0/50085.0),
    (float)(125.0/192.0 - 451.0/720.0),
    (float)(-2187.0/6784.0 + 12231.0/42400.0),
    (float)(11.0/84.0 - 649.0/6300.0),
    (float)(-1.0/60.0)
};
__constant__ float c_midv[7] = {
    (float)(6025192743.0/30085553152.0/2.0), 0.f,
    (float)(51252292925.0/65400821598.0/2.0),
    (float)(-2691868925.0/45128329728.0/2.0),
    (float)(187940372067.0/1594534317056.0/2.0),
    (float)(-1776094331.0/19743644256.0/2.0),
    (float)(11237099.0/235043384.0/2.0)
};

// ---------------------------------------------------------------------------
// Fused MLP layer: out[64 x NOUTL] = act(A @ W + b), A in smem K-major
// ---------------------------------------------------------------------------
template<int KD, int NOUTL, bool RELU, bool TOSMEM>
__device__ __forceinline__ void mlp_layer(
    const float* __restrict__ At,    // smem [KD][LDA] K-major (col=row-of-batch)
    const float* __restrict__ Wg,    // global [KD][ldw] row-major
    int ldw,
    const float* __restrict__ bias,
    float* __restrict__ Bs,          // smem staging [128][64]
    float* __restrict__ OutT,        // smem K-major out (if TOSMEM)
    float* __restrict__ OutG,        // global out, NS cols (if !TOSMEM)
    int row0)
{
    const int tid = threadIdx.x;
    const int tx  = tid & 15;        // output-col group
    const int ty  = tid >> 4;        // batch-row group
    #pragma unroll
    for (int nc0 = 0; nc0 < NOUTL; nc0 += 64) {
        float acc[4][4] = {{0.f,0.f,0.f,0.f},{0.f,0.f,0.f,0.f},
                           {0.f,0.f,0.f,0.f},{0.f,0.f,0.f,0.f}};
        #pragma unroll
        for (int kh = 0; kh < KD; kh += 128) {
            // cooperative load of W chunk [128][64] into smem (float4 coalesced)
            for (int i = tid; i < 128*16; i += 256) {
                int kr = i >> 4, n4 = (i & 15) << 2;
                *(float4*)(Bs + kr*64 + n4) =
                    *(const float4*)(Wg + (size_t)(kh + kr)*ldw + nc0 + n4);
            }
            __syncthreads();
            #pragma unroll 4
            for (int k = 0; k < 128; ++k) {
                float4 a4 = *(const float4*)(At + (kh + k)*LDA + (ty << 2));
                float4 b4 = *(const float4*)(Bs + k*64 + (tx << 2));
                float av[4] = {a4.x, a4.y, a4.z, a4.w};
                float bv[4] = {b4.x, b4.y, b4.z, b4.w};
                #pragma unroll
                for (int ii = 0; ii < 4; ii++)
                    #pragma unroll
                    for (int jj = 0; jj < 4; jj++)
                        acc[ii][jj] = fmaf(av[ii], bv[jj], acc[ii][jj]);
            }
            __syncthreads();
        }
        if constexpr (TOSMEM) {
            #pragma unroll
            for (int jj = 0; jj < 4; jj++) {
                int col = nc0 + (tx << 2) + jj;
                float bj = bias[col];
                float4 o;
                o.x = acc[0][jj] + bj; o.y = acc[1][jj] + bj;
                o.z = acc[2][jj] + bj; o.w = acc[3][jj] + bj;
                if (RELU) {
                    o.x = fmaxf(o.x, 0.f); o.y = fmaxf(o.y, 0.f);
                    o.z = fmaxf(o.z, 0.f); o.w = fmaxf(o.w, 0.f);
                }
                *(float4*)(OutT + col*LDA + (ty << 2)) = o;
            }
        } else {
            float4 bb = *(const float4*)(bias + nc0 + (tx << 2));
            #pragma unroll
            for (int ii = 0; ii < 4; ii++) {
                int r = row0 + (ty << 2) + ii;
                float4 o;
                o.x = acc[ii][0] + bb.x; o.y = acc[ii][1] + bb.y;
                o.z = acc[ii][2] + bb.z; o.w = acc[ii][3] + bb.w;
                *(float4*)(OutG + (size_t)r*NS + nc0 + (tx << 2)) = o;
            }
        }
    }
}

// ---------------------------------------------------------------------------
// Stage kernel: build yi = y + dt*sum(beta*k), compute f(yi) -> k slot.
//  stage = -1 : f0 eval (yi = y),           out slot k0slot
//  stage = -2 : init probe (yi = y + h0*f0), out slot 1
//  stage = 1..6 : dopri stages; stage 6 also writes y1 into the other y buffer
// ---------------------------------------------------------------------------
__global__ void __launch_bounds__(256, 1)
stage_kernel(const float* __restrict__ W1, const float* __restrict__ b1,
             const float* __restrict__ W2, const float* __restrict__ b2,
             const float* __restrict__ W3, const float* __restrict__ b3,
             int stage)
{
    if (stage >= 1 && g_ctrl.done) return;

    extern __shared__ float sm[];
    float* A_T  = sm;                       // [128][LDA]
    float* H1_T = sm + 128*LDA;             // [256][LDA]
    float* H2_T = H1_T + 256*LDA;           // [256][LDA]
    float* Bs   = H2_T + 256*LDA;           // [128][64]

    const int tid  = threadIdx.x;
    const int row0 = blockIdx.x * ROWS_PB;
    const int cur  = g_ctrl.cur;
    const int k0s  = g_ctrl.k0slot;
    const float dt = g_ctrl.dt;
    const float h0 = g_ctrl.h0;
    const float* y = g_ybuf[cur];
    float* ynext   = g_ybuf[cur ^ 1];

    const float* kparr[6];
    kparr[0] = g_k[k0s];
    kparr[1] = g_k[1]; kparr[2] = g_k[2]; kparr[3] = g_k[3];
    kparr[4] = g_k[4]; kparr[5] = g_k[5];

    float coef[6];
    int nk, outslot;
    if (stage == -1)      { nk = 0; outslot = k0s; }
    else if (stage == -2) { nk = 1; coef[0] = h0; outslot = 1; }
    else {
        nk = stage;
        #pragma unroll
        for (int j = 0; j < 6; ++j) coef[j] = dt * c_beta[stage-1][j];
        outslot = (stage < 6) ? stage : (k0s ^ 6);
    }
    float* kout = g_k[outslot];

    // phase 0: build stage input into A_T (K-major); stage 6 also emits y1
    for (int i = tid; i < ROWS_PB*NS; i += 256) {
        int r = i >> 7, cc = i & 127;
        size_t g = (size_t)(row0 + r)*NS + cc;
        float v = y[g];
        for (int j = 0; j < nk; ++j)
            v = fmaf(coef[j], kparr[j][g], v);
        if (stage == 6) ynext[g] = v;
        A_T[cc*LDA + r] = v;
    }
    __syncthreads();

    mlp_layer<128, 256, true,  true >(A_T,  W1, 256, b1, Bs, H1_T, nullptr, 0);
    __syncthreads();
    mlp_layer<256, 256, true,  true >(H1_T, W2, 256, b2, Bs, H2_T, nullptr, 0);
    __syncthreads();
    mlp_layer<256, 128, false, false>(H2_T, W3, 128, b3, Bs, nullptr, kout, row0);
}

// ---------------------------------------------------------------------------
// Reductions
// ---------------------------------------------------------------------------
__device__ __forceinline__ double block_reduce256(double v) {
    __shared__ double sh[256];
    sh[threadIdx.x] = v;
    __syncthreads();
    #pragma unroll
    for (int s = 128; s > 0; s >>= 1) {
        if (threadIdx.x < s) sh[threadIdx.x] += sh[threadIdx.x + s];
        __syncthreads();
    }
    double r = sh[0];
    __syncthreads();
    return r;
}

__global__ void y0_build(const float* __restrict__ x)
{
    for (size_t i = (size_t)blockIdx.x*blockDim.x + threadIdx.x; i < NEL;
         i += (size_t)gridDim.x*blockDim.x) {
        size_t r = i >> 7; int cc = (int)(i & 127);
        g_ybuf[0][i] = (cc < DIN) ? x[r*DIN + cc] : 0.f;
    }
}

__global__ void d01_reduce()
{
    double s0 = 0.0, s1 = 0.0;
    for (size_t i = (size_t)blockIdx.x*blockDim.x + threadIdx.x; i < NEL;
         i += (size_t)gridDim.x*blockDim.x) {
        float y0 = g_ybuf[0][i];
        float f0 = g_k[0][i];
        float sc = ATOLv + RTOLv * fabsf(y0);
        float a = y0 / sc, b = f0 / sc;
        s0 += (double)a * (double)a;
        s1 += (double)b * (double)b;
    }
    double r0 = block_reduce256(s0);
    double r1 = block_reduce256(s1);
    if (threadIdx.x == 0) {
        atomicAdd(&g_ctrl.sum0, r0);
        atomicAdd(&g_ctrl.sum1, r1);
    }
}

__global__ void d2_reduce()
{
    double s2 = 0.0;
    for (size_t i = (size_t)blockIdx.x*blockDim.x + threadIdx.x; i < NEL;
         i += (size_t)gridDim.x*blockDim.x) {
        float y0 = g_ybuf[0][i];
        float sc = ATOLv + RTOLv * fabsf(y0);
        float d = (g_k[1][i] - g_k[0][i]) / sc;
        s2 += (double)d * (double)d;
    }
    double r2 = block_reduce256(s2);
    if (threadIdx.x == 0) atomicAdd(&g_ctrl.sum2, r2);
}

__global__ void err_reduce()
{
    if (g_ctrl.done) return;
    const int k0s = g_ctrl.k0slot;
    const float dt = g_ctrl.dt;
    const float* y  = g_ybuf[g_ctrl.cur];
    const float* y1 = g_ybuf[g_ctrl.cur ^ 1];
    const float* k0 = g_k[k0s];
    const float* k6 = g_k[k0s ^ 6];
    double s = 0.0;
    for (size_t i = (size_t)blockIdx.x*blockDim.x + threadIdx.x; i < NEL;
         i += (size_t)gridDim.x*blockDim.x) {
        float e = c_errv[0]*k0[i] + c_errv[2]*g_k[2][i] + c_errv[3]*g_k[3][i]
                + c_errv[4]*g_k[4][i] + c_errv[5]*g_k[5][i] + c_errv[6]*k6[i];
        e *= dt;
        float tol = ATOLv + RTOLv * fmaxf(fabsf(y[i]), fabsf(y1[i]));
        float ratio = e / tol;
        s += (double)ratio * (double)ratio;
    }
    double r = block_reduce256(s);
    if (threadIdx.x == 0) atomicAdd(&g_ctrl.errsum, r);
}

// ---------------------------------------------------------------------------
// Controllers (single thread)
// ---------------------------------------------------------------------------
__global__ void ctrl_init()
{
    g_ctrl.sum0 = 0.0; g_ctrl.sum1 = 0.0; g_ctrl.sum2 = 0.0; g_ctrl.errsum = 0.0;
    g_ctrl.t = 0.f; g_ctrl.dt = 0.f; g_ctrl.dt_last = 0.f; g_ctrl.last_t = 0.f;
    g_ctrl.h0 = 0.f; g_ctrl.d1 = 0.f;
    g_ctrl.done = 0; g_ctrl.cur = 0; g_ctrl.k0slot = 0;
}

__global__ void ctrl_h0()
{
    float d0 = (float)sqrt(g_ctrl.sum0);
    float d1 = (float)sqrt(g_ctrl.sum1);
    float h0 = (d0 < 1e-5f || d1 < 1e-5f) ? 1e-6f : 0.01f * d0 / d1;
    g_ctrl.h0 = h0;
    g_ctrl.d1 = d1;
}

__global__ void ctrl_dt0()
{
    float h0 = g_ctrl.h0;
    float d1 = g_ctrl.d1;
    float d2 = (float)sqrt(g_ctrl.sum2) / h0;
    float h1;
    if (d1 <= 1e-15f && d2 <= 1e-15f)
        h1 = fmaxf(1e-6f, h0 * 1e-3f);
    else
        h1 = powf(0.01f / fmaxf(d1, d2), 0.2f);   // (0.01/max)^(1/(order+1)), order=4
    g_ctrl.dt = fminf(100.f * h0, h1);
    g_ctrl.t = 0.f;
    g_ctrl.last_t = 0.f;
    g_ctrl.errsum = 0.0;
}

__global__ void ctrl_update()
{
    if (g_ctrl.done) return;
    float err = (float)sqrt(g_ctrl.errsum / (double)NEL);
    // optimal_step_size(dt, err): safety=0.9, ifactor=10, dfactor=0.2, order=5
    float dfac = (err < 1.f) ? 1.f : 0.2f;
    float factor = fminf(10.f, fmaxf(powf(err, -0.2f) * 0.9f, dfac));
    float dtnew = (err == 0.f) ? g_ctrl.dt * 10.f : g_ctrl.dt * factor;
    dtnew = fmaxf(dtnew, 0.f);
    if (err <= 1.f) {               // accept
        g_ctrl.last_t = g_ctrl.t;
        g_ctrl.t      = g_ctrl.t + g_ctrl.dt;
        g_ctrl.dt_last = g_ctrl.dt;
        g_ctrl.cur    ^= 1;
        g_ctrl.k0slot ^= 6;         // FSAL: k7 becomes next k1
        if (g_ctrl.t >= 1.0f) g_ctrl.done = 1;
    }
    g_ctrl.dt = dtnew;
    g_ctrl.errsum = 0.0;
}

// ---------------------------------------------------------------------------
// Final: 4th-order interpolation at t=1, then linear layer @ Wl + bl
// ---------------------------------------------------------------------------
__global__ void __launch_bounds__(256)
final_kernel(const float* __restrict__ Wl, const float* __restrict__ bl,
             float* __restrict__ out)
{
    __shared__ float yt_s[64*132];
    __shared__ float wl_s[128*NOUTC];
    __shared__ float bl_s[NOUTC];

    const int tid = threadIdx.x;
    const int row0 = blockIdx.x * 64;

    for (int i = tid; i < 128*NOUTC; i += 256) wl_s[i] = Wl[i];
    if (tid < NOUTC) bl_s[tid] = bl[tid];

    const int cur = g_ctrl.cur;
    const int k0s = g_ctrl.k0slot;
    const float dtl = g_ctrl.dt_last;
    const float s  = (1.0f - g_ctrl.last_t) / (g_ctrl.t - g_ctrl.last_t);
    const float* yprev = g_ybuf[cur ^ 1];  // y at start of last accepted step
    const float* ycur  = g_ybuf[cur];      // y after last accepted step
    const float* k0p = g_k[k0s ^ 6];       // accepted step's k1 (pre-flip slot)
    const float* k6p = g_k[k0s];           // accepted step's k7

    for (int i = tid; i < 64*NS; i += 256) {
        int r = i >> 7, cc = i & 127;
        size_t g = (size_t)(row0 + r)*NS + cc;
        float y0e = yprev[g];
        float y1e = ycur[g];
        float k0v = k0p[g], k6v = k6p[g];
        float kmid = c_midv[0]*k0v + c_midv[2]*g_k[2][g] + c_midv[3]*g_k[3][g]
                   + c_midv[4]*g_k[4][g] + c_midv[5]*g_k[5][g] + c_midv[6]*k6v;
        float ymid = y0e + dtl * kmid;
        float dy0 = dtl * k0v, dy1 = dtl * k6v;
        float a = -2.f*dy0 + 2.f*dy1 -  8.f*y0e -  8.f*y1e + 16.f*ymid;
        float b =  5.f*dy0 - 3.f*dy1 + 18.f*y0e + 14.f*y1e - 32.f*ymid;
        float c = -4.f*dy0 +     dy1 - 11.f*y0e -  5.f*y1e + 16.f*ymid;
        float d = dy0;
        float e = y0e;
        yt_s[r*132 + cc] = (((a*s + b)*s + c)*s + d)*s + e;
    }
    __syncthreads();

    for (int idx = tid; idx < 64*NOUTC; idx += 256) {
        int r = idx / NOUTC, c = idx % NOUTC;
        float acc = bl_s[c];
        const float* yr = yt_s + r*132;
        #pragma unroll 8
        for (int kk = 0; kk < NS; ++kk)
            acc = fmaf(yr[kk], wl_s[kk*NOUTC + c], acc);
        out[(size_t)(row0 + r)*NOUTC + c] = acc;
    }
}

// ---------------------------------------------------------------------------
// Launch: fully graph-capturable static schedule
// ---------------------------------------------------------------------------
extern "C" void kernel_launch(void* const* d_in, const int* in_sizes, int n_in,
                              void* d_out, int out_size)
{
    const float* x  = (const float*)d_in[0];
    const float* W1 = (const float*)d_in[1];
    const float* b1 = (const float*)d_in[2];
    const float* W2 = (const float*)d_in[3];
    const float* b2 = (const float*)d_in[4];
    const float* W3 = (const float*)d_in[5];
    const float* b3 = (const float*)d_in[6];
    const float* Wl = (const float*)d_in[7];
    const float* bl = (const float*)d_in[8];
    float* out = (float*)d_out;

    cudaFuncSetAttribute(stage_kernel,
                         cudaFuncAttributeMaxDynamicSharedMemorySize, SMEM_BYTES);

    // --- init: y0, f0, Hairer initial step size ---
    ctrl_init<<<1, 1>>>();
    y0_build<<<2048, 256>>>(x);
    stage_kernel<<<NBLK, 256, SMEM_BYTES>>>(W1, b1, W2, b2, W3, b3, -1);
    d01_reduce<<<2048, 256>>>();
    ctrl_h0<<<1, 1>>>();
    stage_kernel<<<NBLK, 256, SMEM_BYTES>>>(W1, b1, W2, b2, W3, b3, -2);
    d2_reduce<<<2048, 256>>>();
    ctrl_dt0<<<1, 1>>>();

    // --- adaptive dopri5 attempts (early-exit when t >= 1) ---
    for (int it = 0; it < MAXIT; ++it) {
        for (int s = 1; s <= 6; ++s)
            stage_kernel<<<NBLK, 256, SMEM_BYTES>>>(W1, b1, W2, b2, W3, b3, s);
        err_reduce<<<2048, 256>>>();
        ctrl_update<<<1, 1>>>();
    }

    // --- interpolate to t=1 and apply final linear layer ---
    final_kernel<<<NBLK, 256>>>(Wl, bl, out);
}

// round 4
// speedup vs baseline: 1.5500x; 1.5500x over previous
#include <cuda_runtime.h>
#include <math.h>
#include <stdint.h>

// ---------------------------------------------------------------------------
// Problem constants
// ---------------------------------------------------------------------------
#define BATCH   65536
#define DIN     118
#define NS      128          // ODE state dim (118 + 10 aug)
#define NH      256          // hidden dim
#define NOUTC   10           // output dim
#define NEL     (BATCH*NS)   // 8388608 state elements
#define ROWS_PB 64           // batch rows per block in fused MLP
#define NBLK    (BATCH/ROWS_PB)   // 1024 blocks
#define MAXIT   20           // attempt budget (timing-proven <= 6 attempts)
#define RTOLv   1e-3f
#define ATOLv   1e-3f
#define LDA     68           // smem K-major row stride (64 rows + 4 pad)
#define KCH     32           // K chunk staged through smem

// smem: A_T[128][LDA] + H1_T[256][LDA] + H2_T[256][LDA] + Bs[32][256]
#define SMEM_FLOATS (128*LDA + 256*LDA + 256*LDA + KCH*256)
#define SMEM_BYTES  (SMEM_FLOATS*4)

// ---------------------------------------------------------------------------
// Device global scratch (static __device__ arrays: no runtime allocation)
// ---------------------------------------------------------------------------
__device__ float g_ybuf[2][NEL];   // double-buffered state y
__device__ float g_k[7][NEL];      // RK stages; slots {0,6} swap as k1/k7 (FSAL)

struct Ctrl {
    double sum0, sum1, sum2, errsum;
    float  t, dt, dt_last, last_t, h0, d1;
    int    done, cur, k0slot;
};
__device__ Ctrl g_ctrl;

// ---------------------------------------------------------------------------
// Dopri5 tableau (exactly as jax.experimental.ode, double -> float)
// ---------------------------------------------------------------------------
__constant__ float c_beta[6][6] = {
    {(float)(1.0/5.0), 0.f, 0.f, 0.f, 0.f, 0.f},
    {(float)(3.0/40.0), (float)(9.0/40.0), 0.f, 0.f, 0.f, 0.f},
    {(float)(44.0/45.0), (float)(-56.0/15.0), (float)(32.0/9.0), 0.f, 0.f, 0.f},
    {(float)(19372.0/6561.0), (float)(-25360.0/2187.0), (float)(64448.0/6561.0),
     (float)(-212.0/729.0), 0.f, 0.f},
    {(float)(9017.0/3168.0), (float)(-355.0/33.0), (float)(46732.0/5247.0),
     (float)(49.0/176.0), (float)(-5103.0/18656.0), 0.f},
    {(float)(35.0/384.0), 0.f, (float)(500.0/1113.0), (float)(125.0/192.0),
     (float)(-2187.0/6784.0), (float)(11.0/84.0)}
};
__constant__ float c_errv[7] = {
    (float)(35.0/384.0 - 1951.0/21600.0), 0.f,
    (float)(500.0/1113.0 - 22642.0/50085.0),
    (float)(125.0/192.0 - 451.0/720.0),
    (float)(-2187.0/6784.0 + 12231.0/42400.0),
    (float)(11.0/84.0 - 649.0/6300.0),
    (float)(-1.0/60.0)
};
__constant__ float c_midv[7] = {
    (float)(6025192743.0/30085553152.0/2.0), 0.f,
    (float)(51252292925.0/65400821598.0/2.0),
    (float)(-2691868925.0/45128329728.0/2.0),
    (float)(187940372067.0/1594534317056.0/2.0),
    (float)(-1776094331.0/19743644256.0/2.0),
    (float)(11237099.0/235043384.0/2.0)
};

// ---------------------------------------------------------------------------
// f32x2 packed-FMA helpers (FFMA2: 2x fp32 FLOPs per issue on sm_103a)
// ---------------------------------------------------------------------------
__device__ __forceinline__ void fma2(unsigned long long &d,
                                     unsigned long long a,
                                     unsigned long long b) {
    asm("fma.rn.f32x2 %0, %1, %2, %0;" : "+l"(d) : "l"(a), "l"(b));
}
__device__ __forceinline__ unsigned long long dup2(float b) {
    unsigned long long r;
    asm("mov.b64 %0, {%1, %1};" : "=l"(r) : "f"(b));
    return r;
}
__device__ __forceinline__ float2 unpack2(unsigned long long v) {
    float2 r;
    asm("mov.b64 {%0, %1}, %2;" : "=f"(r.x), "=f"(r.y) : "l"(v));
    return r;
}

// ---------------------------------------------------------------------------
// Fused MLP layer with f32x2 microtile.
// Thread map: tx = tid&7 -> row group (8 rows), ty = tid>>3 -> col group.
// Layers 1/2: NOUTL=256, CW=8 cols/thread. Layer 3: NOUTL=128, CW=4.
// A operand read from smem K-major [KD][LDA]; W staged in KCH-row chunks.
// ---------------------------------------------------------------------------
template<int KD, int NOUTL, bool RELU, bool TOSMEM>
__device__ __forceinline__ void mlp_layer(
    const float* __restrict__ At,    // smem [KD][LDA] K-major
    const float* __restrict__ Wg,    // global [KD][NOUTL] row-major
    const float* __restrict__ bias,
    float* __restrict__ Bs,          // smem staging [KCH][NOUTL]
    float* __restrict__ OutT,        // smem K-major out (if TOSMEM)
    float* __restrict__ OutG,        // global out, NS cols (if !TOSMEM)
    int row0)
{
    constexpr int CW = NOUTL / 32;   // cols per thread (8 or 4)
    const int tid = threadIdx.x;
    const int tx  = tid & 7;         // row group
    const int ty  = tid >> 3;        // col group (0..31)

    unsigned long long acc[CW][4];
    #pragma unroll
    for (int c = 0; c < CW; ++c)
        #pragma unroll
        for (int r = 0; r < 4; ++r) acc[c][r] = 0ull;

    #pragma unroll
    for (int kh = 0; kh < KD; kh += KCH) {
        // stage W chunk [KCH][NOUTL] into smem (coalesced float4)
        #pragma unroll
        for (int i = tid; i < KCH*NOUTL/4; i += 256) {
            int kr = i / (NOUTL/4), c4 = i % (NOUTL/4);
            *(float4*)(Bs + kr*NOUTL + c4*4) =
                *(const float4*)(Wg + (size_t)(kh + kr)*NOUTL + c4*4);
        }
        __syncthreads();

        #pragma unroll 2
        for (int k = 0; k < KCH; ++k) {
            const float* arow = At + (kh + k)*LDA + tx*8;
            ulonglong2 a01 = *(const ulonglong2*)arow;       // rows 0-3 packed
            ulonglong2 a23 = *(const ulonglong2*)(arow + 4); // rows 4-7 packed
            unsigned long long av[4] = {a01.x, a01.y, a23.x, a23.y};

            const float* brow = Bs + k*NOUTL + ty*CW;
            float bv[CW];
            *(float4*)bv = *(const float4*)brow;
            if constexpr (CW == 8)
                *(float4*)(bv + 4) = *(const float4*)(brow + 4);

            #pragma unroll
            for (int c = 0; c < CW; ++c) {
                unsigned long long bd = dup2(bv[c]);
                #pragma unroll
                for (int r = 0; r < 4; ++r)
                    fma2(acc[c][r], av[r], bd);
            }
        }
        __syncthreads();
    }

    if constexpr (TOSMEM) {
        #pragma unroll
        for (int c = 0; c < CW; ++c) {
            int col = ty*CW + c;
            float bj = bias[col];
            float2 p0 = unpack2(acc[c][0]);
            float2 p1 = unpack2(acc[c][1]);
            float2 p2 = unpack2(acc[c][2]);
            float2 p3 = unpack2(acc[c][3]);
            float4 v0 = {p0.x + bj, p0.y + bj, p1.x + bj, p1.y + bj};
            float4 v1 = {p2.x + bj, p2.y + bj, p3.x + bj, p3.y + bj};
            if (RELU) {
                v0.x = fmaxf(v0.x, 0.f); v0.y = fmaxf(v0.y, 0.f);
                v0.z = fmaxf(v0.z, 0.f); v0.w = fmaxf(v0.w, 0.f);
                v1.x = fmaxf(v1.x, 0.f); v1.y = fmaxf(v1.y, 0.f);
                v1.z = fmaxf(v1.z, 0.f); v1.w = fmaxf(v1.w, 0.f);
            }
            *(float4*)(OutT + col*LDA + tx*8)     = v0;
            *(float4*)(OutT + col*LDA + tx*8 + 4) = v1;
        }
    } else {
        // CW == 4: transpose in registers, one float4 per output row
        float4 bb = *(const float4*)(bias + ty*4);
        float o[8][4];
        #pragma unroll
        for (int c = 0; c < 4; ++c) {
            float bj = (c == 0) ? bb.x : (c == 1) ? bb.y : (c == 2) ? bb.z : bb.w;
            #pragma unroll
            for (int r = 0; r < 4; ++r) {
                float2 p = unpack2(acc[c][r]);
                o[2*r  ][c] = p.x + bj;
                o[2*r+1][c] = p.y + bj;
            }
        }
        #pragma unroll
        for (int r = 0; r < 8; ++r) {
            float4 v = {o[r][0], o[r][1], o[r][2], o[r][3]};
            *(float4*)(OutG + (size_t)(row0 + tx*8 + r)*NS + ty*4) = v;
        }
    }
}

// ---------------------------------------------------------------------------
// Stage kernel: build yi = y + dt*sum(beta*k), compute f(yi) -> k slot.
//  stage = -1 : f0 eval (yi = y),            out slot k0slot
//  stage = -2 : init probe (yi = y + h0*f0), out slot 1
//  stage = 1..6 : dopri stages; stage 6 also writes y1 into the other y buffer
// ---------------------------------------------------------------------------
__global__ void __launch_bounds__(256, 1)
stage_kernel(const float* __restrict__ W1, const float* __restrict__ b1,
             const float* __restrict__ W2, const float* __restrict__ b2,
             const float* __restrict__ W3, const float* __restrict__ b3,
             int stage)
{
    if (stage >= 1 && g_ctrl.done) return;

    extern __shared__ float sm[];
    float* A_T  = sm;                       // [128][LDA]
    float* H1_T = sm + 128*LDA;             // [256][LDA]
    float* H2_T = H1_T + 256*LDA;           // [256][LDA]
    float* Bs   = H2_T + 256*LDA;           // [KCH][256]

    const int tid  = threadIdx.x;
    const int row0 = blockIdx.x * ROWS_PB;
    const int cur  = g_ctrl.cur;
    const int k0s  = g_ctrl.k0slot;
    const float dt = g_ctrl.dt;
    const float h0 = g_ctrl.h0;
    const float* y = g_ybuf[cur];
    float* ynext   = g_ybuf[cur ^ 1];

    const float* kparr[6];
    kparr[0] = g_k[k0s];
    kparr[1] = g_k[1]; kparr[2] = g_k[2]; kparr[3] = g_k[3];
    kparr[4] = g_k[4]; kparr[5] = g_k[5];

    float coef[6];
    int nk, outslot;
    if (stage == -1)      { nk = 0; outslot = k0s; }
    else if (stage == -2) { nk = 1; coef[0] = h0; outslot = 1; }
    else {
        nk = stage;
        #pragma unroll
        for (int j = 0; j < 6; ++j) coef[j] = dt * c_beta[stage-1][j];
        outslot = (stage < 6) ? stage : (k0s ^ 6);
    }
    float* kout = g_k[outslot];

    // phase 0: build stage input into A_T (K-major), float4 global traffic;
    // stage 6 also emits y1
    for (int i = tid; i < ROWS_PB*NS/4; i += 256) {
        int r  = i >> 5;         // NS/4 = 32 float4 per row
        int c4 = i & 31;
        size_t g4 = ((size_t)(row0 + r)*NS >> 2) + c4;
        float4 v = ((const float4*)y)[g4];
        for (int j = 0; j < nk; ++j) {
            float4 kv = ((const float4*)kparr[j])[g4];
            v.x = fmaf(coef[j], kv.x, v.x);
            v.y = fmaf(coef[j], kv.y, v.y);
            v.z = fmaf(coef[j], kv.z, v.z);
            v.w = fmaf(coef[j], kv.w, v.w);
        }
        if (stage == 6) ((float4*)ynext)[g4] = v;
        int cc = c4 * 4;
        A_T[(cc+0)*LDA + r] = v.x;
        A_T[(cc+1)*LDA + r] = v.y;
        A_T[(cc+2)*LDA + r] = v.z;
        A_T[(cc+3)*LDA + r] = v.w;
    }
    __syncthreads();

    mlp_layer<128, 256, true,  true >(A_T,  W1, b1, Bs, H1_T, nullptr, 0);
    __syncthreads();
    mlp_layer<256, 256, true,  true >(H1_T, W2, b2, Bs, H2_T, nullptr, 0);
    __syncthreads();
    mlp_layer<256, 128, false, false>(H2_T, W3, b3, Bs, nullptr, kout, row0);
}

// ---------------------------------------------------------------------------
// Reductions
// ---------------------------------------------------------------------------
__device__ __forceinline__ double block_reduce256(double v) {
    __shared__ double sh[256];
    sh[threadIdx.x] = v;
    __syncthreads();
    #pragma unroll
    for (int s = 128; s > 0; s >>= 1) {
        if (threadIdx.x < s) sh[threadIdx.x] += sh[threadIdx.x + s];
        __syncthreads();
    }
    double r = sh[0];
    __syncthreads();
    return r;
}

__global__ void y0_build(const float* __restrict__ x)
{
    for (size_t i = (size_t)blockIdx.x*blockDim.x + threadIdx.x; i < NEL;
         i += (size_t)gridDim.x*blockDim.x) {
        size_t r = i >> 7; int cc = (int)(i & 127);
        g_ybuf[0][i] = (cc < DIN) ? x[r*DIN + cc] : 0.f;
    }
}

__global__ void d01_reduce()
{
    double s0 = 0.0, s1 = 0.0;
    for (size_t i = (size_t)blockIdx.x*blockDim.x + threadIdx.x; i < NEL/4;
         i += (size_t)gridDim.x*blockDim.x) {
        float4 y0 = ((const float4*)g_ybuf[0])[i];
        float4 f0 = ((const float4*)g_k[0])[i];
        float sc, a, b;
        sc = ATOLv + RTOLv*fabsf(y0.x); a = y0.x/sc; b = f0.x/sc;
        s0 += (double)a*a; s1 += (double)b*b;
        sc = ATOLv + RTOLv*fabsf(y0.y); a = y0.y/sc; b = f0.y/sc;
        s0 += (double)a*a; s1 += (double)b*b;
        sc = ATOLv + RTOLv*fabsf(y0.z); a = y0.z/sc; b = f0.z/sc;
        s0 += (double)a*a; s1 += (double)b*b;
        sc = ATOLv + RTOLv*fabsf(y0.w); a = y0.w/sc; b = f0.w/sc;
        s0 += (double)a*a; s1 += (double)b*b;
    }
    double r0 = block_reduce256(s0);
    double r1 = block_reduce256(s1);
    if (threadIdx.x == 0) {
        atomicAdd(&g_ctrl.sum0, r0);
        atomicAdd(&g_ctrl.sum1, r1);
    }
}

__global__ void d2_reduce()
{
    double s2 = 0.0;
    for (size_t i = (size_t)blockIdx.x*blockDim.x + threadIdx.x; i < NEL/4;
         i += (size_t)gridDim.x*blockDim.x) {
        float4 y0 = ((const float4*)g_ybuf[0])[i];
        float4 k0 = ((const float4*)g_k[0])[i];
        float4 k1 = ((const float4*)g_k[1])[i];
        float sc, d;
        sc = ATOLv + RTOLv*fabsf(y0.x); d = (k1.x - k0.x)/sc; s2 += (double)d*d;
        sc = ATOLv + RTOLv*fabsf(y0.y); d = (k1.y - k0.y)/sc; s2 += (double)d*d;
        sc = ATOLv + RTOLv*fabsf(y0.z); d = (k1.z - k0.z)/sc; s2 += (double)d*d;
        sc = ATOLv + RTOLv*fabsf(y0.w); d = (k1.w - k0.w)/sc; s2 += (double)d*d;
    }
    double r2 = block_reduce256(s2);
    if (threadIdx.x == 0) atomicAdd(&g_ctrl.sum2, r2);
}

__global__ void err_reduce()
{
    if (g_ctrl.done) return;
    const int k0s = g_ctrl.k0slot;
    const float dt = g_ctrl.dt;
    const float4* y  = (const float4*)g_ybuf[g_ctrl.cur];
    const float4* y1 = (const float4*)g_ybuf[g_ctrl.cur ^ 1];
    const float4* k0 = (const float4*)g_k[k0s];
    const float4* k6 = (const float4*)g_k[k0s ^ 6];
    const float4* k2 = (const float4*)g_k[2];
    const float4* k3 = (const float4*)g_k[3];
    const float4* k4 = (const float4*)g_k[4];
    const float4* k5 = (const float4*)g_k[5];
    double s = 0.0;
    for (size_t i = (size_t)blockIdx.x*blockDim.x + threadIdx.x; i < NEL/4;
         i += (size_t)gridDim.x*blockDim.x) {
        float4 a0 = k0[i], a2 = k2[i], a3 = k3[i], a4 = k4[i], a5 = k5[i], a6 = k6[i];
        float4 yv = y[i], y1v = y1[i];
        float e, tol, ratio;
        e = dt*(c_errv[0]*a0.x + c_errv[2]*a2.x + c_errv[3]*a3.x
              + c_errv[4]*a4.x + c_errv[5]*a5.x + c_errv[6]*a6.x);
        tol = ATOLv + RTOLv*fmaxf(fabsf(yv.x), fabsf(y1v.x));
        ratio = e/tol; s += (double)ratio*ratio;
        e = dt*(c_errv[0]*a0.y + c_errv[2]*a2.y + c_errv[3]*a3.y
              + c_errv[4]*a4.y + c_errv[5]*a5.y + c_errv[6]*a6.y);
        tol = ATOLv + RTOLv*fmaxf(fabsf(yv.y), fabsf(y1v.y));
        ratio = e/tol; s += (double)ratio*ratio;
        e = dt*(c_errv[0]*a0.z + c_errv[2]*a2.z + c_errv[3]*a3.z
              + c_errv[4]*a4.z + c_errv[5]*a5.z + c_errv[6]*a6.z);
        tol = ATOLv + RTOLv*fmaxf(fabsf(yv.z), fabsf(y1v.z));
        ratio = e/tol; s += (double)ratio*ratio;
        e = dt*(c_errv[0]*a0.w + c_errv[2]*a2.w + c_errv[3]*a3.w
              + c_errv[4]*a4.w + c_errv[5]*a5.w + c_errv[6]*a6.w);
        tol = ATOLv + RTOLv*fmaxf(fabsf(yv.w), fabsf(y1v.w));
        ratio = e/tol; s += (double)ratio*ratio;
    }
    double r = block_reduce256(s);
    if (threadIdx.x == 0) atomicAdd(&g_ctrl.errsum, r);
}

// ---------------------------------------------------------------------------
// Controllers (single thread) — identical semantics to the passing round
// ---------------------------------------------------------------------------
__global__ void ctrl_init()
{
    g_ctrl.sum0 = 0.0; g_ctrl.sum1 = 0.0; g_ctrl.sum2 = 0.0; g_ctrl.errsum = 0.0;
    g_ctrl.t = 0.f; g_ctrl.dt = 0.f; g_ctrl.dt_last = 0.f; g_ctrl.last_t = 0.f;
    g_ctrl.h0 = 0.f; g_ctrl.d1 = 0.f;
    g_ctrl.done = 0; g_ctrl.cur = 0; g_ctrl.k0slot = 0;
}

__global__ void ctrl_h0()
{
    float d0 = (float)sqrt(g_ctrl.sum0);
    float d1 = (float)sqrt(g_ctrl.sum1);
    float h0 = (d0 < 1e-5f || d1 < 1e-5f) ? 1e-6f : 0.01f * d0 / d1;
    g_ctrl.h0 = h0;
    g_ctrl.d1 = d1;
}

__global__ void ctrl_dt0()
{
    float h0 = g_ctrl.h0;
    float d1 = g_ctrl.d1;
    float d2 = (float)sqrt(g_ctrl.sum2) / h0;
    float h1;
    if (d1 <= 1e-15f && d2 <= 1e-15f)
        h1 = fmaxf(1e-6f, h0 * 1e-3f);
    else
        h1 = powf(0.01f / fmaxf(d1, d2), 0.2f);
    g_ctrl.dt = fminf(100.f * h0, h1);
    g_ctrl.t = 0.f;
    g_ctrl.last_t = 0.f;
    g_ctrl.errsum = 0.0;
}

__global__ void ctrl_update()
{
    if (g_ctrl.done) return;
    float err = (float)sqrt(g_ctrl.errsum / (double)NEL);
    float dfac = (err < 1.f) ? 1.f : 0.2f;
    float factor = fminf(10.f, fmaxf(powf(err, -0.2f) * 0.9f, dfac));
    float dtnew = (err == 0.f) ? g_ctrl.dt * 10.f : g_ctrl.dt * factor;
    dtnew = fmaxf(dtnew, 0.f);
    if (err <= 1.f) {               // accept
        g_ctrl.last_t = g_ctrl.t;
        g_ctrl.t      = g_ctrl.t + g_ctrl.dt;
        g_ctrl.dt_last = g_ctrl.dt;
        g_ctrl.cur    ^= 1;
        g_ctrl.k0slot ^= 6;         // FSAL: k7 becomes next k1
        if (g_ctrl.t >= 1.0f) g_ctrl.done = 1;
    }
    g_ctrl.dt = dtnew;
    g_ctrl.errsum = 0.0;
}

// ---------------------------------------------------------------------------
// Final: 4th-order interpolation at t=1, then linear layer @ Wl + bl
// ---------------------------------------------------------------------------
__global__ void __launch_bounds__(256)
final_kernel(const float* __restrict__ Wl, const float* __restrict__ bl,
             float* __restrict__ out)
{
    __shared__ float yt_s[64*132];
    __shared__ float wl_s[128*NOUTC];
    __shared__ float bl_s[NOUTC];

    const int tid = threadIdx.x;
    const int row0 = blockIdx.x * 64;

    for (int i = tid; i < 128*NOUTC; i += 256) wl_s[i] = Wl[i];
    if (tid < NOUTC) bl_s[tid] = bl[tid];

    const int cur = g_ctrl.cur;
    const int k0s = g_ctrl.k0slot;
    const float dtl = g_ctrl.dt_last;
    const float s  = (1.0f - g_ctrl.last_t) / (g_ctrl.t - g_ctrl.last_t);
    const float* yprev = g_ybuf[cur ^ 1];  // y at start of last accepted step
    const float* ycur  = g_ybuf[cur];      // y after last accepted step
    const float* k0p = g_k[k0s ^ 6];       // accepted step's k1 (pre-flip slot)
    const float* k6p = g_k[k0s];           // accepted step's k7

    for (int i = tid; i < 64*NS; i += 256) {
        int r = i >> 7, cc = i & 127;
        size_t g = (size_t)(row0 + r)*NS + cc;
        float y0e = yprev[g];
        float y1e = ycur[g];
        float k0v = k0p[g], k6v = k6p[g];
        float kmid = c_midv[0]*k0v + c_midv[2]*g_k[2][g] + c_midv[3]*g_k[3][g]
                   + c_midv[4]*g_k[4][g] + c_midv[5]*g_k[5][g] + c_midv[6]*k6v;
        float ymid = y0e + dtl * kmid;
        float dy0 = dtl * k0v, dy1 = dtl * k6v;
        float a = -2.f*dy0 + 2.f*dy1 -  8.f*y0e -  8.f*y1e + 16.f*ymid;
        float b =  5.f*dy0 - 3.f*dy1 + 18.f*y0e + 14.f*y1e - 32.f*ymid;
        float c = -4.f*dy0 +     dy1 - 11.f*y0e -  5.f*y1e + 16.f*ymid;
        float d = dy0;
        float e = y0e;
        yt_s[r*132 + cc] = (((a*s + b)*s + c)*s + d)*s + e;
    }
    __syncthreads();

    for (int idx = tid; idx < 64*NOUTC; idx += 256) {
        int r = idx / NOUTC, c = idx % NOUTC;
        float acc = bl_s[c];
        const float* yr = yt_s + r*132;
        #pragma unroll 8
        for (int kk = 0; kk < NS; ++kk)
            acc = fmaf(yr[kk], wl_s[kk*NOUTC + c], acc);
        out[(size_t)(row0 + r)*NOUTC + c] = acc;
    }
}

// ---------------------------------------------------------------------------
// Launch: fully graph-capturable static schedule
// ---------------------------------------------------------------------------
extern "C" void kernel_launch(void* const* d_in, const int* in_sizes, int n_in,
                              void* d_out, int out_size)
{
    const float* x  = (const float*)d_in[0];
    const float* W1 = (const float*)d_in[1];
    const float* b1 = (const float*)d_in[2];
    const float* W2 = (const float*)d_in[3];
    const float* b2 = (const float*)d_in[4];
    const float* W3 = (const float*)d_in[5];
    const float* b3 = (const float*)d_in[6];
    const float* Wl = (const float*)d_in[7];
    const float* bl = (const float*)d_in[8];
    float* out = (float*)d_out;

    cudaFuncSetAttribute(stage_kernel,
                         cudaFuncAttributeMaxDynamicSharedMemorySize, SMEM_BYTES);

    // --- init: y0, f0, Hairer initial step size ---
    ctrl_init<<<1, 1>>>();
    y0_build<<<2048, 256>>>(x);
    stage_kernel<<<NBLK, 256, SMEM_BYTES>>>(W1, b1, W2, b2, W3, b3, -1);
    d01_reduce<<<2048, 256>>>();
    ctrl_h0<<<1, 1>>>();
    stage_kernel<<<NBLK, 256, SMEM_BYTES>>>(W1, b1, W2, b2, W3, b3, -2);
    d2_reduce<<<2048, 256>>>();
    ctrl_dt0<<<1, 1>>>();

    // --- adaptive dopri5 attempts (early-exit when t >= 1) ---
    for (int it = 0; it < MAXIT; ++it) {
        for (int s = 1; s <= 6; ++s)
            stage_kernel<<<NBLK, 256, SMEM_BYTES>>>(W1, b1, W2, b2, W3, b3, s);
        err_reduce<<<2048, 256>>>();
        ctrl_update<<<1, 1>>>();
    }

    // --- interpolate to t=1 and apply final linear layer ---
    final_kernel<<<NBLK, 256>>>(Wl, bl, out);
}